// round 1
// baseline (speedup 1.0000x reference)
#include <cuda_runtime.h>

// Problem shape (fixed by setup_inputs): B=1024, S=512, H=64, input dim 1.
#define HD     64
#define G4     256          // 4*H gates
#define BATCH  1024
#define SEQ    512
#define RPB    8            // batch rows per block
#define NT     256          // threads per block (one gate per thread)
#define WSZ    (G4*HD)      // 16384 floats per weight matrix

// Shared memory layout (float offsets)
#define OFF_WH1  0
#define OFF_WI2  16384
#define OFF_WH2  32768
#define OFF_B1   49152
#define OFF_B2   49408
#define OFF_WX1  49664
#define OFF_WLIN 49920
#define OFF_H1   50048      // RPB*HD = 512
#define OFF_C1   50560
#define OFF_H2   51072
#define OFF_C2   51584
#define OFF_G    52096      // RPB*G4 = 2048
#define OFF_XS   54144      // RPB
#define SMEM_FLOATS 54160
#define SMEM_BYTES  (SMEM_FLOATS * 4)

__device__ __forceinline__ float sigf(float x) {
    return __fdividef(1.0f, 1.0f + __expf(-x));
}
__device__ __forceinline__ float tanhfast(float x) {
    // tanh(x) = 2*sigmoid(2x) - 1 ; __expf is 2-ulp accurate, safe for rel_err 1e-3
    return fmaf(2.0f, __fdividef(1.0f, 1.0f + __expf(-2.0f * x)), -1.0f);
}

__global__ __launch_bounds__(NT, 1)
void lstm_kernel(const float* __restrict__ x,
                 const float* __restrict__ Wih1,
                 const float* __restrict__ Whh1,
                 const float* __restrict__ bih1,
                 const float* __restrict__ bhh1,
                 const float* __restrict__ Wih2,
                 const float* __restrict__ Whh2,
                 const float* __restrict__ bih2,
                 const float* __restrict__ bhh2,
                 const float* __restrict__ Wlin,
                 const float* __restrict__ blin,
                 float* __restrict__ out)
{
    extern __shared__ float smf[];
    const int tid  = threadIdx.x;
    const int row0 = blockIdx.x * RPB;

    // ---- Preload weights into SMEM with XOR swizzle on 16B chunks ----
    // Row g (64 floats = 16 chunks); chunk cj stored at g*16 + (cj ^ (g&15)).
    // Per-gate reads (lane = gate) then land in distinct 16B bank groups per phase.
    {
        const float4* s1 = (const float4*)Whh1;
        const float4* s2 = (const float4*)Wih2;
        const float4* s3 = (const float4*)Whh2;
        float4* d1 = (float4*)(smf + OFF_WH1);
        float4* d2 = (float4*)(smf + OFF_WI2);
        float4* d3 = (float4*)(smf + OFF_WH2);
        for (int i = tid; i < WSZ / 4; i += NT) {
            int g = i >> 4, c = i & 15;
            int dstIdx = (g << 4) + (c ^ (g & 15));
            d1[dstIdx] = s1[i];
            d2[dstIdx] = s2[i];
            d3[dstIdx] = s3[i];
        }
    }
    if (tid < G4) {
        smf[OFF_B1  + tid] = bih1[tid] + bhh1[tid];
        smf[OFF_B2  + tid] = bih2[tid] + bhh2[tid];
        smf[OFF_WX1 + tid] = Wih1[tid];           // W_ih1 is (256,1)
    }
    if (tid < HD) smf[OFF_WLIN + tid] = Wlin[tid]; // W_lin is (1,64)
    for (int i = tid; i < RPB * HD; i += NT) {
        smf[OFF_H1 + i] = 0.0f; smf[OFF_C1 + i] = 0.0f;
        smf[OFF_H2 + i] = 0.0f; smf[OFF_C2 + i] = 0.0f;
    }
    if (tid < RPB) smf[OFF_XS + tid] = x[(row0 + tid) * SEQ];
    const float bl = blin[0];
    __syncthreads();

    const int gsw = tid & 15;
    const float4* wh1_4 = (const float4*)(smf + OFF_WH1) + (tid << 4);
    const float4* wi2_4 = (const float4*)(smf + OFF_WI2) + (tid << 4);
    const float4* wh2_4 = (const float4*)(smf + OFF_WH2) + (tid << 4);
    const float4* h1_4  = (const float4*)(smf + OFF_H1);
    const float4* h2_4  = (const float4*)(smf + OFF_H2);
    const float bb1 = smf[OFF_B1 + tid];
    const float bb2 = smf[OFF_B2 + tid];
    const float wx  = smf[OFF_WX1 + tid];
    float* gs = smf + OFF_G;

    for (int t = 0; t < SEQ; ++t) {
        float acc[RPB];

        // ---- Phase 1: layer-1 gates.  gate(tid) for all 8 rows ----
        #pragma unroll
        for (int r = 0; r < RPB; ++r) acc[r] = fmaf(smf[OFF_XS + r], wx, bb1);
        #pragma unroll
        for (int c = 0; c < 16; ++c) {
            float4 w = wh1_4[c ^ gsw];
            #pragma unroll
            for (int r = 0; r < RPB; ++r) {
                float4 h = h1_4[(r << 4) + c];
                acc[r] = fmaf(w.x, h.x, acc[r]);
                acc[r] = fmaf(w.y, h.y, acc[r]);
                acc[r] = fmaf(w.z, h.z, acc[r]);
                acc[r] = fmaf(w.w, h.w, acc[r]);
            }
        }
        #pragma unroll
        for (int r = 0; r < RPB; ++r) gs[(r << 8) + tid] = acc[r];
        __syncthreads();

        // ---- Phase 2: layer-1 elementwise update (2 (row,unit) pairs/thread) ----
        #pragma unroll
        for (int u = 0; u < 2; ++u) {
            int p = tid + u * NT;          // 0..511
            int r = p >> 6, j = p & 63;
            const float* gr = gs + (r << 8);
            float ig = sigf(gr[j]);
            float fg = sigf(gr[64 + j]);
            float gg = tanhfast(gr[128 + j]);
            float og = sigf(gr[192 + j]);
            float cc = fmaf(fg, smf[OFF_C1 + (r << 6) + j], ig * gg);
            smf[OFF_C1 + (r << 6) + j] = cc;
            smf[OFF_H1 + (r << 6) + j] = og * tanhfast(cc);
        }
        __syncthreads();

        // ---- Phase 3: layer-2 gates = Wih2@h1 + Whh2@h2 + b2 ----
        #pragma unroll
        for (int r = 0; r < RPB; ++r) acc[r] = bb2;
        #pragma unroll
        for (int c = 0; c < 16; ++c) {
            float4 w = wi2_4[c ^ gsw];
            #pragma unroll
            for (int r = 0; r < RPB; ++r) {
                float4 h = h1_4[(r << 4) + c];
                acc[r] = fmaf(w.x, h.x, acc[r]);
                acc[r] = fmaf(w.y, h.y, acc[r]);
                acc[r] = fmaf(w.z, h.z, acc[r]);
                acc[r] = fmaf(w.w, h.w, acc[r]);
            }
        }
        #pragma unroll
        for (int c = 0; c < 16; ++c) {
            float4 w = wh2_4[c ^ gsw];
            #pragma unroll
            for (int r = 0; r < RPB; ++r) {
                float4 h = h2_4[(r << 4) + c];
                acc[r] = fmaf(w.x, h.x, acc[r]);
                acc[r] = fmaf(w.y, h.y, acc[r]);
                acc[r] = fmaf(w.z, h.z, acc[r]);
                acc[r] = fmaf(w.w, h.w, acc[r]);
            }
        }
        #pragma unroll
        for (int r = 0; r < RPB; ++r) gs[(r << 8) + tid] = acc[r];
        __syncthreads();

        // ---- Phase 4a: layer-2 elementwise update; preload next x ----
        #pragma unroll
        for (int u = 0; u < 2; ++u) {
            int p = tid + u * NT;
            int r = p >> 6, j = p & 63;
            const float* gr = gs + (r << 8);
            float ig = sigf(gr[j]);
            float fg = sigf(gr[64 + j]);
            float gg = tanhfast(gr[128 + j]);
            float og = sigf(gr[192 + j]);
            float cc = fmaf(fg, smf[OFF_C2 + (r << 6) + j], ig * gg);
            smf[OFF_C2 + (r << 6) + j] = cc;
            smf[OFF_H2 + (r << 6) + j] = og * tanhfast(cc);
        }
        if (tid < RPB && t + 1 < SEQ)
            smf[OFF_XS + tid] = x[(row0 + tid) * SEQ + t + 1];
        __syncthreads();

        // ---- Phase 4b: output = dot(h2[row], Wlin) + blin (warp per row) ----
        {
            int wr = tid >> 5, l = tid & 31;
            float v = fmaf(smf[OFF_H2 + (wr << 6) + l], smf[OFF_WLIN + l],
                           smf[OFF_H2 + (wr << 6) + 32 + l] * smf[OFF_WLIN + 32 + l]);
            #pragma unroll
            for (int s = 16; s; s >>= 1) v += __shfl_xor_sync(0xffffffffu, v, s);
            if (l == 0) out[(row0 + wr) * SEQ + t] = v + bl;
        }
        __syncthreads();
    }
}

extern "C" void kernel_launch(void* const* d_in, const int* in_sizes, int n_in,
                              void* d_out, int out_size)
{
    (void)in_sizes; (void)n_in; (void)out_size;
    // Inputs (metadata order): input_t, W_ih1, W_hh1, b_ih1, b_hh1,
    //                          W_ih2, W_hh2, b_ih2, b_hh2, W_lin, b_lin, future_preds(=0)
    cudaFuncSetAttribute(lstm_kernel,
                         cudaFuncAttributeMaxDynamicSharedMemorySize, SMEM_BYTES);
    lstm_kernel<<<BATCH / RPB, NT, SMEM_BYTES>>>(
        (const float*)d_in[0],
        (const float*)d_in[1],  (const float*)d_in[2],
        (const float*)d_in[3],  (const float*)d_in[4],
        (const float*)d_in[5],  (const float*)d_in[6],
        (const float*)d_in[7],  (const float*)d_in[8],
        (const float*)d_in[9],  (const float*)d_in[10],
        (float*)d_out);
}

// round 2
// speedup vs baseline: 1.3977x; 1.3977x over previous
#include <cuda_runtime.h>

// B=1024, S=512, H=64, input dim 1, future_preds=0.
#define HD    64
#define G4    256
#define BATCH 1024
#define SEQ   512
#define RPB   8
#define NT    512

// Shared memory layout (float offsets)
#define OFF_W1   0        // swizzled Whh1: 16384 floats
#define OFF_P    16384    // partials: 4 slices x 4 rowpairs x 256 gates x float2 = 8192
#define OFF_H1T  24576    // hT1[64][8]
#define OFF_H2T  25088    // hT2[64][8]
#define OFF_XS   25600    // 8
#define OFF_WL   25608    // 64
#define OFF_RED  25672    // 16
#define SMEM_FLOATS 25696
#define SMEM_BYTES  (SMEM_FLOATS * 4)

typedef unsigned long long u64t;

__device__ __forceinline__ float sigf(float x) {
    return __fdividef(1.0f, 1.0f + __expf(-x));
}
__device__ __forceinline__ float tanhfast(float x) {
    return fmaf(2.0f, __fdividef(1.0f, 1.0f + __expf(-2.0f * x)), -1.0f);
}
__device__ __forceinline__ unsigned su32(const void* p) {
    unsigned a;
    asm("{.reg .u64 t; cvta.to.shared.u64 t, %1; cvt.u32.u64 %0, t;}" : "=r"(a) : "l"(p));
    return a;
}
__device__ __forceinline__ u64t pk2(float x) {
    u64t r; asm("mov.b64 %0,{%1,%1};" : "=l"(r) : "f"(x)); return r;
}
__device__ __forceinline__ u64t mk2(float lo, float hi) {
    u64t r; asm("mov.b64 %0,{%1,%2};" : "=l"(r) : "f"(lo), "f"(hi)); return r;
}
// d.lo += a.lo*b.lo ; d.hi += a.hi*b.hi   (packed f32x2 FMA, sm_100+)
#define FMA2(d,a,b) asm("fma.rn.f32x2 %0,%1,%2,%0;" : "+l"(d) : "l"(a), "l"(b))
// 16B shared load as two packed row-pairs
#define LDSV4(h0,h1,addr) asm volatile("ld.shared.v2.b64 {%0,%1},[%2];" : "=l"(h0), "=l"(h1) : "r"(addr))
#define STSH64(addr,v)    asm volatile("st.shared.b64 [%0],%1;" :: "r"(addr), "l"(v))

__global__ __launch_bounds__(NT, 1)
void lstm_kernel(const float* __restrict__ x,
                 const float* __restrict__ Wih1,
                 const float* __restrict__ Whh1,
                 const float* __restrict__ bih1,
                 const float* __restrict__ bhh1,
                 const float* __restrict__ Wih2,
                 const float* __restrict__ Whh2,
                 const float* __restrict__ bih2,
                 const float* __restrict__ bhh2,
                 const float* __restrict__ Wlin,
                 const float* __restrict__ blin,
                 float* __restrict__ out)
{
    extern __shared__ float smf[];
    const int tid  = threadIdx.x;
    const int row0 = blockIdx.x * RPB;

    // Thread decomposition: quarter q (16 units), gate pair {ga, gb}
    const int q  = tid >> 7;          // 0..3
    const int i  = tid & 127;
    const int ga = i;
    const int gb = i + 128;
    // Elementwise mapping (fixed across steps): row r, unit j
    const int er = tid >> 6;          // 0..7
    const int ej = tid & 63;          // 0..63

    // ---- Load Whh1 into SMEM with XOR swizzle on 16B chunks ----
    {
        const float4* src = (const float4*)Whh1;
        float4* dst = (float4*)(smf + OFF_W1);
        for (int idx = tid; idx < 4096; idx += NT) {
            int g = idx >> 4, c = idx & 15;
            dst[(g << 4) + (c ^ (g & 15))] = src[idx];
        }
    }
    // ---- Layer-2 weight slices into registers (16 units each, 4 arrays) ----
    float wi2a[16], wi2b[16], wh2a[16], wh2b[16];
    {
        const float4* pa = (const float4*)(Wih2 + ga * HD + q * 16);
        const float4* pb = (const float4*)(Wih2 + gb * HD + q * 16);
        const float4* pc = (const float4*)(Whh2 + ga * HD + q * 16);
        const float4* pd = (const float4*)(Whh2 + gb * HD + q * 16);
        #pragma unroll
        for (int c = 0; c < 4; ++c) {
            ((float4*)wi2a)[c] = pa[c];
            ((float4*)wi2b)[c] = pb[c];
            ((float4*)wh2a)[c] = pc[c];
            ((float4*)wh2b)[c] = pd[c];
        }
    }
    const float b1a = bih1[ga] + bhh1[ga];
    const float b1b = bih1[gb] + bhh1[gb];
    const float b2a = bih2[ga] + bhh2[ga];
    const float b2b = bih2[gb] + bhh2[gb];
    const float wxa = Wih1[ga];
    const float wxb = Wih1[gb];
    const float bl  = blin[0];

    for (int idx = tid; idx < 1024; idx += NT) smf[OFF_H1T + idx] = 0.0f; // hT1+hT2
    if (tid < 64) smf[OFF_WL + tid] = Wlin[tid];
    if (tid < 16) smf[OFF_RED + tid] = 0.0f;
    if (tid < 8)  smf[OFF_XS + tid] = x[(row0 + tid) * SEQ];
    float c1r = 0.0f, c2r = 0.0f;
    __syncthreads();

    const unsigned smb   = su32(smf);
    const unsigned h1t_a = smb + OFF_H1T * 4;
    const unsigned h2t_a = smb + OFF_H2T * 4;
    // partial store bases: slice s=q, rowpair p stride 2048B, gate*8B
    const unsigned pAa = smb + (OFF_P + q * 2048 + ga * 2) * 4;
    const unsigned pBa = smb + (OFF_P + q * 2048 + gb * 2) * 4;
    const float4* w1s4 = (const float4*)(smf + OFF_W1);
    const int ga16 = ga << 4, gb16 = gb << 4, kxa = ga & 15, q4 = q << 2;

    float xn = 0.0f;
    for (int t = 0; t < SEQ; ++t) {
        // ---- prefetch next x; deferred output store for step t-1 ----
        if (tid < 8) {
            int tt = (t + 1 < SEQ) ? (t + 1) : t;
            xn = x[(row0 + tid) * SEQ + tt];
            if (t > 0)
                out[(row0 + tid) * SEQ + (t - 1)] =
                    smf[OFF_RED + 2 * tid] + smf[OFF_RED + 2 * tid + 1] + bl;
        }

        // ================= P1: layer-1 gate partials =================
        {
            u64t a0, a1, a2, a3, b0, b1, b2, b3;
            if (q == 0) {
                float x0 = smf[OFF_XS + 0], x1 = smf[OFF_XS + 1];
                float x2 = smf[OFF_XS + 2], x3 = smf[OFF_XS + 3];
                float x4 = smf[OFF_XS + 4], x5 = smf[OFF_XS + 5];
                float x6 = smf[OFF_XS + 6], x7 = smf[OFF_XS + 7];
                a0 = mk2(fmaf(x0, wxa, b1a), fmaf(x1, wxa, b1a));
                a1 = mk2(fmaf(x2, wxa, b1a), fmaf(x3, wxa, b1a));
                a2 = mk2(fmaf(x4, wxa, b1a), fmaf(x5, wxa, b1a));
                a3 = mk2(fmaf(x6, wxa, b1a), fmaf(x7, wxa, b1a));
                b0 = mk2(fmaf(x0, wxb, b1b), fmaf(x1, wxb, b1b));
                b1 = mk2(fmaf(x2, wxb, b1b), fmaf(x3, wxb, b1b));
                b2 = mk2(fmaf(x4, wxb, b1b), fmaf(x5, wxb, b1b));
                b3 = mk2(fmaf(x6, wxb, b1b), fmaf(x7, wxb, b1b));
            } else {
                a0 = a1 = a2 = a3 = 0ull;
                b0 = b1 = b2 = b3 = 0ull;
            }
            #pragma unroll
            for (int c = 0; c < 4; ++c) {
                float4 wa = w1s4[ga16 + ((q4 + c) ^ kxa)];
                float4 wb = w1s4[gb16 + ((q4 + c) ^ kxa)];
                const float* wap = (const float*)&wa;
                const float* wbp = (const float*)&wb;
                #pragma unroll
                for (int u = 0; u < 4; ++u) {
                    unsigned ha = h1t_a + (((q << 4) + (c << 2) + u) << 5);
                    u64t h01, h23, h45, h67;
                    LDSV4(h01, h23, ha);
                    LDSV4(h45, h67, ha + 16);
                    u64t wa2 = pk2(wap[u]);
                    u64t wb2 = pk2(wbp[u]);
                    FMA2(a0, wa2, h01); FMA2(a1, wa2, h23);
                    FMA2(a2, wa2, h45); FMA2(a3, wa2, h67);
                    FMA2(b0, wb2, h01); FMA2(b1, wb2, h23);
                    FMA2(b2, wb2, h45); FMA2(b3, wb2, h67);
                }
            }
            STSH64(pAa,          a0); STSH64(pAa + 2048, a1);
            STSH64(pAa + 4096,   a2); STSH64(pAa + 6144, a3);
            STSH64(pBa,          b0); STSH64(pBa + 2048, b1);
            STSH64(pBa + 4096,   b2); STSH64(pBa + 6144, b3);
        }
        __syncthreads();

        // ================= P2: layer-1 elementwise =================
        {
            float gv[4];
            #pragma unroll
            for (int gi = 0; gi < 4; ++gi) {
                int g = ej + (gi << 6);
                int base = OFF_P + ((er >> 1) << 9) + (g << 1) + (er & 1);
                gv[gi] = (smf[base] + smf[base + 2048]) +
                         (smf[base + 4096] + smf[base + 6144]);
            }
            float ig = sigf(gv[0]);
            float fg = sigf(gv[1]);
            float gg = tanhfast(gv[2]);
            float og = sigf(gv[3]);
            c1r = fmaf(fg, c1r, ig * gg);
            smf[OFF_H1T + (ej << 3) + er] = og * tanhfast(c1r);
        }
        __syncthreads();

        // ================= P3: layer-2 gate partials =================
        {
            u64t a0, a1, a2, a3, b0, b1, b2, b3;
            if (q == 0) {
                a0 = a1 = a2 = a3 = pk2(b2a);
                b0 = b1 = b2 = b3 = pk2(b2b);
            } else {
                a0 = a1 = a2 = a3 = 0ull;
                b0 = b1 = b2 = b3 = 0ull;
            }
            #pragma unroll
            for (int k = 0; k < 16; ++k) {
                unsigned off = ((q << 4) + k) << 5;
                u64t p01, p23, p45, p67, s01, s23, s45, s67;
                LDSV4(p01, p23, h1t_a + off);
                LDSV4(p45, p67, h1t_a + off + 16);
                LDSV4(s01, s23, h2t_a + off);
                LDSV4(s45, s67, h2t_a + off + 16);
                u64t wia = pk2(wi2a[k]);
                u64t wib = pk2(wi2b[k]);
                u64t wha = pk2(wh2a[k]);
                u64t whb = pk2(wh2b[k]);
                FMA2(a0, wia, p01); FMA2(a1, wia, p23);
                FMA2(a2, wia, p45); FMA2(a3, wia, p67);
                FMA2(b0, wib, p01); FMA2(b1, wib, p23);
                FMA2(b2, wib, p45); FMA2(b3, wib, p67);
                FMA2(a0, wha, s01); FMA2(a1, wha, s23);
                FMA2(a2, wha, s45); FMA2(a3, wha, s67);
                FMA2(b0, whb, s01); FMA2(b1, whb, s23);
                FMA2(b2, whb, s45); FMA2(b3, whb, s67);
            }
            STSH64(pAa,          a0); STSH64(pAa + 2048, a1);
            STSH64(pAa + 4096,   a2); STSH64(pAa + 6144, a3);
            STSH64(pBa,          b0); STSH64(pBa + 2048, b1);
            STSH64(pBa + 4096,   b2); STSH64(pBa + 6144, b3);
        }
        __syncthreads();

        // ================= P4: layer-2 elementwise + output =================
        {
            float gv[4];
            #pragma unroll
            for (int gi = 0; gi < 4; ++gi) {
                int g = ej + (gi << 6);
                int base = OFF_P + ((er >> 1) << 9) + (g << 1) + (er & 1);
                gv[gi] = (smf[base] + smf[base + 2048]) +
                         (smf[base + 4096] + smf[base + 6144]);
            }
            float ig = sigf(gv[0]);
            float fg = sigf(gv[1]);
            float gg = tanhfast(gv[2]);
            float og = sigf(gv[3]);
            c2r = fmaf(fg, c2r, ig * gg);
            float h2v = og * tanhfast(c2r);
            smf[OFF_H2T + (ej << 3) + er] = h2v;

            float v = h2v * smf[OFF_WL + ej];
            #pragma unroll
            for (int s = 16; s; s >>= 1) v += __shfl_xor_sync(0xffffffffu, v, s);
            if ((tid & 31) == 0) smf[OFF_RED + (tid >> 5)] = v;
            if (tid < 8) smf[OFF_XS + tid] = xn;
        }
        __syncthreads();
    }

    if (tid < 8)
        out[(row0 + tid) * SEQ + (SEQ - 1)] =
            smf[OFF_RED + 2 * tid] + smf[OFF_RED + 2 * tid + 1] + bl;
}

extern "C" void kernel_launch(void* const* d_in, const int* in_sizes, int n_in,
                              void* d_out, int out_size)
{
    (void)in_sizes; (void)n_in; (void)out_size;
    cudaFuncSetAttribute(lstm_kernel,
                         cudaFuncAttributeMaxDynamicSharedMemorySize, SMEM_BYTES);
    lstm_kernel<<<BATCH / RPB, NT, SMEM_BYTES>>>(
        (const float*)d_in[0],
        (const float*)d_in[1],  (const float*)d_in[2],
        (const float*)d_in[3],  (const float*)d_in[4],
        (const float*)d_in[5],  (const float*)d_in[6],
        (const float*)d_in[7],  (const float*)d_in[8],
        (const float*)d_in[9],  (const float*)d_in[10],
        (float*)d_out);
}

// round 6
// speedup vs baseline: 1.5323x; 1.0963x over previous
#include <cuda_runtime.h>

// B=1024, S=512, H=64, input dim 1, future_preds=0.
#define SEQ   512
#define BATCH 1024
#define RPB   8
#define NT    256

// Shared float offsets
#define OFF_W1  0        // pre-shuffled Whh1: 16384 floats (64KB)
#define OFF_P   16384    // gate partials: 8192 floats (32KB)
#define OFF_H1  24576    // hT1[rp][j] u64 pairs: 512 floats
#define OFF_H2  25088    // hT2: 512
#define OFF_XS  25600    // 8
#define OFF_RED 25608    // 16
#define SMEM_FLOATS 25632
#define SMEM_BYTES  (SMEM_FLOATS * 4)

typedef unsigned long long u64t;

__device__ __forceinline__ float sigf(float x) {
    return __fdividef(1.0f, 1.0f + __expf(-x));
}
__device__ __forceinline__ float tanhfast(float x) {
    return fmaf(2.0f, __fdividef(1.0f, 1.0f + __expf(-2.0f * x)), -1.0f);
}
__device__ __forceinline__ unsigned su32(const void* p) {
    unsigned a;
    asm("{.reg .u64 t; cvta.to.shared.u64 t, %1; cvt.u32.u64 %0, t;}" : "=r"(a) : "l"(p));
    return a;
}
__device__ __forceinline__ u64t pk2(float x) {
    u64t r; asm("mov.b64 %0,{%1,%1};" : "=l"(r) : "f"(x)); return r;
}
__device__ __forceinline__ u64t mk2(float lo, float hi) {
    u64t r; asm("mov.b64 %0,{%1,%2};" : "=l"(r) : "f"(lo), "f"(hi)); return r;
}
#define UNPK(lo,hi,v)  asm("mov.b64 {%0,%1},%2;" : "=f"(lo), "=f"(hi) : "l"(v))
#define FMA2(d,a,b)    asm("fma.rn.f32x2 %0,%1,%2,%0;" : "+l"(d) : "l"(a), "l"(b))
#define ADD2(d,a)      asm("add.rn.f32x2 %0,%0,%1;" : "+l"(d) : "l"(a))
#define LDSV4(h0,h1,addr) asm volatile("ld.shared.v2.b64 {%0,%1},[%2];" : "=l"(h0), "=l"(h1) : "r"(addr))
#define LDS64(h,addr)     asm volatile("ld.shared.b64 %0,[%1];" : "=l"(h) : "r"(addr))
#define STSH64(addr,v)    asm volatile("st.shared.b64 [%0],%1;" :: "r"(addr), "l"(v))
#define LDS128F(a,b,c,d,addr) asm volatile("ld.shared.v4.f32 {%0,%1,%2,%3},[%4];" : "=f"(a),"=f"(b),"=f"(c),"=f"(d) : "r"(addr))

__global__ __launch_bounds__(NT, 1)
void lstm_kernel(const float* __restrict__ x,
                 const float* __restrict__ Wih1,
                 const float* __restrict__ Whh1,
                 const float* __restrict__ bih1,
                 const float* __restrict__ bhh1,
                 const float* __restrict__ Wih2,
                 const float* __restrict__ Whh2,
                 const float* __restrict__ bih2,
                 const float* __restrict__ bhh2,
                 const float* __restrict__ Wlin,
                 const float* __restrict__ blin,
                 float* __restrict__ out)
{
    extern __shared__ float smf[];
    const int tid  = threadIdx.x;
    const int row0 = blockIdx.x * RPB;
    const int q = tid >> 6;        // K-slice 0..3 (16 units each), also rowpair owned
    const int j = tid & 63;        // unit
    const int swz = j & 15;

    // ---- Pre-shuffle Whh1 into per-thread-contiguous, chunk-swizzled layout ----
    // dst float4 index c = q*1024 + j*16 + slot, slot = (gg*4+kc) ^ (j&15)
    {
        const float4* src = (const float4*)Whh1;
        float4* dst = (float4*)(smf + OFF_W1);
        for (int c = tid; c < 4096; c += NT) {
            int qc = c >> 10, r = c & 1023, jc = r >> 4, slot = r & 15;
            int s2 = slot ^ (jc & 15);
            int gg = s2 >> 2, kc = s2 & 3;
            dst[c] = src[(jc + gg * 64) * 16 + qc * 4 + kc];
        }
    }
    // ---- Layer-2 weights resident in registers: [gate gg][unit k in slice] ----
    float wi2[64], wh2[64];
    #pragma unroll
    for (int gg = 0; gg < 4; ++gg) {
        const float4* pa = (const float4*)(Wih2 + (j + gg * 64) * 64 + q * 16);
        const float4* pb = (const float4*)(Whh2 + (j + gg * 64) * 64 + q * 16);
        #pragma unroll
        for (int c = 0; c < 4; ++c) {
            float4 va = pa[c];
            wi2[gg*16 + c*4 + 0] = va.x; wi2[gg*16 + c*4 + 1] = va.y;
            wi2[gg*16 + c*4 + 2] = va.z; wi2[gg*16 + c*4 + 3] = va.w;
            float4 vb = pb[c];
            wh2[gg*16 + c*4 + 0] = vb.x; wh2[gg*16 + c*4 + 1] = vb.y;
            wh2[gg*16 + c*4 + 2] = vb.z; wh2[gg*16 + c*4 + 3] = vb.w;
        }
    }
    float b1v[4], b2v[4], wxv[4];
    #pragma unroll
    for (int gg = 0; gg < 4; ++gg) {
        int g = j + gg * 64;
        b1v[gg] = bih1[g] + bhh1[g];
        b2v[gg] = bih2[g] + bhh2[g];
        wxv[gg] = Wih1[g];
    }
    const float wlr = Wlin[j];
    const float bl  = blin[0];

    for (int idx = tid; idx < 1024; idx += NT) smf[OFF_H1 + idx] = 0.0f;
    if (tid < 8) smf[OFF_XS + tid] = x[(row0 + tid) * SEQ];
    float c1a = 0.0f, c1b = 0.0f, c2a = 0.0f, c2b = 0.0f;
    __syncthreads();

    const unsigned smb = su32(smf);
    const unsigned h1a = smb + OFF_H1 * 4;
    const unsigned h2a = smb + OFF_H2 * 4;
    const unsigned w1a = smb + OFF_W1 * 4 + q * 16384 + j * 256;
    const unsigned pMine = smb + OFF_P * 4 + q * 8192 + j * 128;
    unsigned pRead[3];
    #pragma unroll
    for (int dq = 1; dq < 4; ++dq)
        pRead[dq - 1] = smb + OFF_P * 4 + (((unsigned)(q + dq) & 3u) * 8192) + j * 128;
    unsigned rslot[4];
    #pragma unroll
    for (int gg = 0; gg < 4; ++gg) rslot[gg] = (unsigned)(((gg * 4 + q) ^ swz) * 8);

    u64t own1[4], own2[4];
    float xn = 0.0f;

    for (int t = 0; t < SEQ; ++t) {
        if (tid < 8) {
            int tt = (t + 1 < SEQ) ? (t + 1) : t;
            xn = x[(row0 + tid) * SEQ + tt];
            if (t > 0)
                out[(row0 + tid) * SEQ + (t - 1)] =
                    smf[OFF_RED + (tid >> 1) * 4 + (tid & 1)] +
                    smf[OFF_RED + (tid >> 1) * 4 + 2 + (tid & 1)] + bl;
        }

        // ============ P1: layer-1 gate partials ============
        {
            u64t acc[4][4];
            if (q == 0) {
                #pragma unroll
                for (int rp = 0; rp < 4; ++rp) {
                    float xa = smf[OFF_XS + 2 * rp], xb = smf[OFF_XS + 2 * rp + 1];
                    #pragma unroll
                    for (int gg = 0; gg < 4; ++gg)
                        acc[gg][rp] = mk2(fmaf(xa, wxv[gg], b1v[gg]),
                                          fmaf(xb, wxv[gg], b1v[gg]));
                }
            } else {
                #pragma unroll
                for (int gg = 0; gg < 4; ++gg)
                    #pragma unroll
                    for (int rp = 0; rp < 4; ++rp) acc[gg][rp] = 0ull;
            }
            #pragma unroll
            for (int kc = 0; kc < 4; ++kc) {
                float w[4][4];
                #pragma unroll
                for (int gg = 0; gg < 4; ++gg) {
                    unsigned a = w1a + (unsigned)((((gg * 4 + kc) ^ swz)) * 16);
                    LDS128F(w[gg][0], w[gg][1], w[gg][2], w[gg][3], a);
                }
                #pragma unroll
                for (int up = 0; up < 2; ++up) {
                    u64t ha[4], hb[4];
                    unsigned kb = (unsigned)((q * 16 + kc * 4 + up * 2) * 8);
                    #pragma unroll
                    for (int rp = 0; rp < 4; ++rp)
                        LDSV4(ha[rp], hb[rp], h1a + rp * 512 + kb);
                    #pragma unroll
                    for (int gg = 0; gg < 4; ++gg) {
                        u64t wA = pk2(w[gg][up * 2]);
                        u64t wB = pk2(w[gg][up * 2 + 1]);
                        #pragma unroll
                        for (int rp = 0; rp < 4; ++rp) {
                            FMA2(acc[gg][rp], wA, ha[rp]);
                            FMA2(acc[gg][rp], wB, hb[rp]);
                        }
                    }
                }
            }
            #pragma unroll
            for (int gg = 0; gg < 4; ++gg)
                #pragma unroll
                for (int rp = 0; rp < 4; ++rp) {
                    if (rp == q) own1[gg] = acc[gg][rp];
                    else STSH64(pMine + (unsigned)(((gg * 4 + rp) ^ swz) * 8), acc[gg][rp]);
                }
        }
        __syncthreads();

        // ============ P2: layer-1 cell update (rows 2q, 2q+1 of unit j) ============
        {
            float gvl[4], gvh[4];
            #pragma unroll
            for (int gg = 0; gg < 4; ++gg) {
                u64t s = own1[gg];
                #pragma unroll
                for (int dq = 0; dq < 3; ++dq) {
                    u64t v; LDS64(v, pRead[dq] + rslot[gg]);
                    ADD2(s, v);
                }
                UNPK(gvl[gg], gvh[gg], s);
            }
            float i0 = sigf(gvl[0]), f0 = sigf(gvl[1]);
            float g0 = tanhfast(gvl[2]), o0 = sigf(gvl[3]);
            c1a = fmaf(f0, c1a, i0 * g0);
            float h0 = o0 * tanhfast(c1a);
            float i1 = sigf(gvh[0]), f1 = sigf(gvh[1]);
            float g1 = tanhfast(gvh[2]), o1 = sigf(gvh[3]);
            c1b = fmaf(f1, c1b, i1 * g1);
            float h1 = o1 * tanhfast(c1b);
            STSH64(h1a + q * 512 + j * 8, mk2(h0, h1));
        }
        __syncthreads();

        // ============ P3: layer-2 gate partials ============
        {
            u64t acc[4][4];
            #pragma unroll
            for (int gg = 0; gg < 4; ++gg) {
                u64t init = (q == 0) ? pk2(b2v[gg]) : 0ull;
                #pragma unroll
                for (int rp = 0; rp < 4; ++rp) acc[gg][rp] = init;
            }
            #pragma unroll
            for (int kc = 0; kc < 4; ++kc)
                #pragma unroll
                for (int up = 0; up < 2; ++up) {
                    u64t ha[4], hb[4];
                    unsigned kb = (unsigned)((q * 16 + kc * 4 + up * 2) * 8);
                    #pragma unroll
                    for (int rp = 0; rp < 4; ++rp)
                        LDSV4(ha[rp], hb[rp], h1a + rp * 512 + kb);
                    #pragma unroll
                    for (int gg = 0; gg < 4; ++gg) {
                        u64t wA = pk2(wi2[gg * 16 + kc * 4 + up * 2]);
                        u64t wB = pk2(wi2[gg * 16 + kc * 4 + up * 2 + 1]);
                        #pragma unroll
                        for (int rp = 0; rp < 4; ++rp) {
                            FMA2(acc[gg][rp], wA, ha[rp]);
                            FMA2(acc[gg][rp], wB, hb[rp]);
                        }
                    }
                }
            #pragma unroll
            for (int kc = 0; kc < 4; ++kc)
                #pragma unroll
                for (int up = 0; up < 2; ++up) {
                    u64t ha[4], hb[4];
                    unsigned kb = (unsigned)((q * 16 + kc * 4 + up * 2) * 8);
                    #pragma unroll
                    for (int rp = 0; rp < 4; ++rp)
                        LDSV4(ha[rp], hb[rp], h2a + rp * 512 + kb);
                    #pragma unroll
                    for (int gg = 0; gg < 4; ++gg) {
                        u64t wA = pk2(wh2[gg * 16 + kc * 4 + up * 2]);
                        u64t wB = pk2(wh2[gg * 16 + kc * 4 + up * 2 + 1]);
                        #pragma unroll
                        for (int rp = 0; rp < 4; ++rp) {
                            FMA2(acc[gg][rp], wA, ha[rp]);
                            FMA2(acc[gg][rp], wB, hb[rp]);
                        }
                    }
                }
            #pragma unroll
            for (int gg = 0; gg < 4; ++gg)
                #pragma unroll
                for (int rp = 0; rp < 4; ++rp) {
                    if (rp == q) own2[gg] = acc[gg][rp];
                    else STSH64(pMine + (unsigned)(((gg * 4 + rp) ^ swz) * 8), acc[gg][rp]);
                }
        }
        __syncthreads();

        // ============ P4: layer-2 cell update + output ============
        {
            float gvl[4], gvh[4];
            #pragma unroll
            for (int gg = 0; gg < 4; ++gg) {
                u64t s = own2[gg];
                #pragma unroll
                for (int dq = 0; dq < 3; ++dq) {
                    u64t v; LDS64(v, pRead[dq] + rslot[gg]);
                    ADD2(s, v);
                }
                UNPK(gvl[gg], gvh[gg], s);
            }
            float i0 = sigf(gvl[0]), f0 = sigf(gvl[1]);
            float g0 = tanhfast(gvl[2]), o0 = sigf(gvl[3]);
            c2a = fmaf(f0, c2a, i0 * g0);
            float h0 = o0 * tanhfast(c2a);
            float i1 = sigf(gvh[0]), f1 = sigf(gvh[1]);
            float g1 = tanhfast(gvh[2]), o1 = sigf(gvh[3]);
            c2b = fmaf(f1, c2b, i1 * g1);
            float h1 = o1 * tanhfast(c2b);
            STSH64(h2a + q * 512 + j * 8, mk2(h0, h1));

            float v0 = h0 * wlr, v1 = h1 * wlr;
            #pragma unroll
            for (int s = 16; s; s >>= 1) {
                v0 += __shfl_xor_sync(0xffffffffu, v0, s);
                v1 += __shfl_xor_sync(0xffffffffu, v1, s);
            }
            if ((tid & 31) == 0) {
                int w = tid >> 5;
                smf[OFF_RED + w * 2]     = v0;
                smf[OFF_RED + w * 2 + 1] = v1;
            }
            if (tid < 8) smf[OFF_XS + tid] = xn;
        }
        __syncthreads();
    }

    if (tid < 8)
        out[(row0 + tid) * SEQ + (SEQ - 1)] =
            smf[OFF_RED + (tid >> 1) * 4 + (tid & 1)] +
            smf[OFF_RED + (tid >> 1) * 4 + 2 + (tid & 1)] + bl;
}

extern "C" void kernel_launch(void* const* d_in, const int* in_sizes, int n_in,
                              void* d_out, int out_size)
{
    (void)in_sizes; (void)n_in; (void)out_size;
    cudaFuncSetAttribute(lstm_kernel,
                         cudaFuncAttributeMaxDynamicSharedMemorySize, SMEM_BYTES);
    lstm_kernel<<<BATCH / RPB, NT, SMEM_BYTES>>>(
        (const float*)d_in[0],
        (const float*)d_in[1],  (const float*)d_in[2],
        (const float*)d_in[3],  (const float*)d_in[4],
        (const float*)d_in[5],  (const float*)d_in[6],
        (const float*)d_in[7],  (const float*)d_in[8],
        (const float*)d_in[9],  (const float*)d_in[10],
        (float*)d_out);
}